// round 12
// baseline (speedup 1.0000x reference)
#include <cuda_runtime.h>
#include <cstdint>
#include <cstddef>

#define NB    32
#define TT    2048
#define MMI   64
#define PPO   64
#define NSTA  512
#define NROWS (NB * TT)
#define KB    16              // scan trace block (time steps)
#define CHUNK 512             // time chunk per fused CTA
#define NCH   (TT / CHUNK)    // 4
#define GRP   64              // timesteps per fused GEMM group
#define ZK    128             // z-IIR block
#define XPAD  516             // X row stride (floats): %4==0, 516%32==4 -> conflict-free
#define CPAD  68              // Cs row stride

__device__ float g_Bu[NROWS * NSTA];
__device__ float g_d [NB * TT];
__device__ float g_z [NB * (TT + 1)];

// ---------------------------------------------------------------------------
__global__ void k_zero_d() {
    int i = blockIdx.x * blockDim.x + threadIdx.x;
    reinterpret_cast<float4*>(g_d)[i] = make_float4(0.f, 0.f, 0.f, 0.f);
}

// ---------------------------------------------------------------------------
// K1: Bu = u @ B^T, fused with anti-diagonal partial sums for d. (unchanged)
// ---------------------------------------------------------------------------
__global__ void __launch_bounds__(256) k_bu(const float* __restrict__ u,
                                            const float* __restrict__ Bm) {
    __shared__ float us[128][33];
    __shared__ float bs[64][33];
    __shared__ float dsh[192];

    const int r0  = blockIdx.x * 128;
    const int n0  = blockIdx.y * 64;
    const int tid = threadIdx.x;
    const int tx  = tid & 15;
    const int ty  = tid >> 4;
    const int lr  = tid >> 3;
    const int lk  = (tid & 7) * 4;

    if (tid < 192) dsh[tid] = 0.f;

    float acc[8][4];
#pragma unroll
    for (int i = 0; i < 8; i++)
#pragma unroll
        for (int j = 0; j < 4; j++) acc[i][j] = 0.0f;

#pragma unroll
    for (int c = 0; c < 2; c++) {
#pragma unroll
        for (int pass = 0; pass < 4; ++pass) {
            int row = lr + pass * 32;
            float4 v = *reinterpret_cast<const float4*>(
                u + (size_t)(r0 + row) * MMI + c * 32 + lk);
            us[row][lk + 0] = v.x; us[row][lk + 1] = v.y;
            us[row][lk + 2] = v.z; us[row][lk + 3] = v.w;
        }
#pragma unroll
        for (int pass = 0; pass < 2; ++pass) {
            int n = lr + pass * 32;
            float4 v = *reinterpret_cast<const float4*>(
                Bm + (size_t)(n0 + n) * MMI + c * 32 + lk);
            bs[n][lk + 0] = v.x; bs[n][lk + 1] = v.y;
            bs[n][lk + 2] = v.z; bs[n][lk + 3] = v.w;
        }
        __syncthreads();
#pragma unroll
        for (int k = 0; k < 32; k++) {
            float av[8], bv[4];
#pragma unroll
            for (int i = 0; i < 8; i++) av[i] = us[ty * 8 + i][k];
#pragma unroll
            for (int j = 0; j < 4; j++) bv[j] = bs[tx * 4 + j][k];
#pragma unroll
            for (int i = 0; i < 8; i++)
#pragma unroll
                for (int j = 0; j < 4; j++)
                    acc[i][j] = fmaf(av[i], bv[j], acc[i][j]);
        }
        __syncthreads();
    }

#pragma unroll
    for (int i = 0; i < 8; i++) {
        float4 v = make_float4(acc[i][0], acc[i][1], acc[i][2], acc[i][3]);
        *reinterpret_cast<float4*>(
            g_Bu + (size_t)(r0 + ty * 8 + i) * NSTA + n0 + tx * 4) = v;
    }

    float dl[11];
#pragma unroll
    for (int q = 0; q < 11; q++) dl[q] = 0.f;
#pragma unroll
    for (int i = 0; i < 8; i++)
#pragma unroll
        for (int j = 0; j < 4; j++) dl[i - j + 3] += acc[i][j];
    const int obase = ty * 8 - tx * 4 + 60;
#pragma unroll
    for (int q = 0; q < 11; q++) atomicAdd(&dsh[obase + q], dl[q]);
    __syncthreads();
    if (tid < 192) {
        int bb  = r0 >> 11;
        int idx = (r0 & 2047) + 448 - n0 + tid;
        if (idx < TT) atomicAdd(&g_d[bb * TT + idx], dsh[tid]);
    }
}

// ---------------------------------------------------------------------------
// K2: scalar 512-tap IIR per batch (unchanged)
// ---------------------------------------------------------------------------
__global__ void __launch_bounds__(512) k_ziir(const float* __restrict__ a) {
    __shared__ float zb[2561];
    __shared__ float as[512];
    __shared__ float gs[ZK];
    __shared__ float bsol[ZK];

    const int b   = blockIdx.x;
    const int tid = threadIdx.x;

    as[tid] = a[tid];
    for (int i = tid; i < 2561; i += 512) zb[i] = 0.f;
    __syncthreads();

    if (tid < 32) {
        const int l = tid;
        for (int c = 0; c < ZK; c += 32) {
            const int q = c + l;
            float H = 0.f;
            for (int j = q - c + 1; j <= q; j++)
                H += as[j - 1] * gs[q - j];
            float inner = 0.f;
            for (int m = 0; m < 32; m++) {
                float v = -(H + inner);
                if (c == 0 && m == 0) v = 1.f;
                float gval = __shfl_sync(0xffffffffu, v, m);
                if (l == m) gs[q] = gval;
                else if (l > m) inner += as[l - m - 1] * gval;
            }
            __syncwarp();
        }
    }
    __syncthreads();

    const float* dp = g_d + (size_t)b * TT;
    const int k4 = (tid >> 2) + 1;
    const int qq = tid & 3;

    for (int blk = 0; blk < TT / ZK; blk++) {
        const int T0 = blk * ZK;
        const int t  = T0 + k4;
        float H = 0.f;
        for (int j = k4 + qq; j <= 512; j += 4)
            H += as[j - 1] * zb[512 + t - j];
        H += __shfl_xor_sync(0xffffffffu, H, 1);
        H += __shfl_xor_sync(0xffffffffu, H, 2);
        if (qq == 0) bsol[k4 - 1] = dp[t - 1] - H;
        __syncthreads();
        float zv = 0.f;
        for (int m = 1 + qq; m <= k4; m += 4)
            zv += gs[k4 - m] * bsol[m - 1];
        zv += __shfl_xor_sync(0xffffffffu, zv, 1);
        zv += __shfl_xor_sync(0xffffffffu, zv, 2);
        if (qq == 0) zb[512 + t] = zv;
        __syncthreads();
    }

    for (int t = tid; t <= TT; t += 512)
        g_z[(size_t)b * (TT + 1) + t] = zb[512 + t];
}

// ---------------------------------------------------------------------------
// K3 FUSED: scan + C-GEMM. x never touches DRAM.
// Per CTA (batch b, chunk c of 512 t): scan diagonally in KB=16 blocks
// (warm-up min(c*512,512) steps, exact), staging stored x rows into smem
// X[64][XPAD]. Every 4 stored blocks, GEMM Y(64t x 64p) = X @ C^T with C
// streamed through smem in 64-col chunks, written straight to y.
// ---------------------------------------------------------------------------
struct FSmem {
    float butile[2][KB * NSTA];   // 65536 B
    float X[GRP][XPAD];           // 132096 B
    float Cs[64][CPAD];           // 17408 B
    float xs[2][NSTA];            // 4096 B
    float fs[NSTA];               // 2048 B
    float zs[2][KB];              // 128 B
};                                // total 221312 B

__device__ __forceinline__ unsigned su32(const void* p) {
    return (unsigned)__cvta_generic_to_shared(p);
}
__device__ __forceinline__ void cp16(void* smem_dst, const void* gsrc) {
    asm volatile("cp.async.cg.shared.global [%0], [%1], 16;"
                 :: "r"(su32(smem_dst)), "l"(gsrc));
}
__device__ __forceinline__ void cp_commit() { asm volatile("cp.async.commit_group;"); }
__device__ __forceinline__ void cp_wait0()  { asm volatile("cp.async.wait_group 0;"); }

__global__ void __launch_bounds__(512, 1) k_fused(const float* __restrict__ a,
                                                  const float* __restrict__ Cm,
                                                  float* __restrict__ y) {
    extern __shared__ char raw[];
    FSmem* s = reinterpret_cast<FSmem*>(raw);
    const int b = blockIdx.x >> 2;   // batch
    const int c = blockIdx.x & 3;    // chunk
    const int i = threadIdx.x;
    const int lane = i & 31;
    const int wrp  = i >> 5;         // 0..15

    s->fs[i] = -a[511 - i];
    s->xs[0][i] = 0.f;

    const int warm    = (c == 0) ? 0 : 512;
    const int base_t  = c * CHUNK - warm;
    const int nblk    = (warm + CHUNK) / KB;
    const int wstore0 = warm / KB;

    const float* bu_g = g_Bu + ((size_t)b * TT + base_t) * NSTA;
    const float* z_g  = g_z + (size_t)b * (TT + 1) + base_t;
    float*       y_b  = y + ((size_t)b * TT + c * CHUNK) * PPO;

    {   // preload Bu tile 0 (KB*NSTA = 8192 floats = 2048 float4)
        float* dst = s->butile[0];
#pragma unroll
        for (int r = 0; r < 4; r++) { int q = i + r * 512; cp16(dst + q * 4, bu_g + q * 4); }
        cp_commit(); cp_wait0();
    }
    if (i < KB) s->zs[0][i] = z_g[i];
    __syncthreads();

    const float fs0 = s->fs[0];

    for (int w = 0; w < nblk; w++) {
        const int cur = w & 1;
        const float* bu  = s->butile[cur];
        const float* xsc = s->xs[cur];
        const float* zsc = s->zs[cur];

        if (w + 1 < nblk) {
            const float* src = bu_g + (size_t)(w + 1) * KB * NSTA;
            float* dst = s->butile[cur ^ 1];
#pragma unroll
            for (int r = 0; r < 4; r++) { int q = i + r * 512; cp16(dst + q * 4, src + q * 4); }
            cp_commit();
            if (i < KB) s->zs[cur ^ 1][i] = z_g[(size_t)(w + 1) * KB + i];
        }

        const bool st     = (w >= wstore0);
        const int  stbase = (w - wstore0) * KB;   // stored step of k=1 (valid if st)
        float v  = (i >= KB) ? xsc[i - KB]        : 0.f;
        float v2 = (i <  KB) ? xsc[NSTA - KB + i] : 0.f;

#pragma unroll
        for (int k = 1; k <= KB; k++) {
            const float zk = zsc[k - 1];
            const int row  = (stbase + k - 1) & (GRP - 1);
            int p = i - KB + k;
            if (p == 0) {
                v = fs0 * zk + bu[(k - 1) * NSTA];
                if (st) s->X[row][0] = v;
            } else if (p > 0) {
                v += s->fs[p] * zk + bu[(k - 1) * NSTA + p];
                if (st) s->X[row][p] = v;
            }
            if (i < KB) {
                int p2 = NSTA - KB + i + k;
                if (p2 < NSTA) {
                    v2 += s->fs[p2] * zk + bu[(k - 1) * NSTA + p2];
                    if (st) s->X[row][p2] = v2;
                }
            }
        }
        s->xs[cur ^ 1][i] = v;

        // ---- GEMM group: after every 4th stored block ----
        if (st && (((w - wstore0) & 3) == 3)) {
            const int g = (w - wstore0) >> 2;          // group 0..7
            __syncthreads();                            // X complete

            float acc[4][2];
#pragma unroll
            for (int ii = 0; ii < 4; ii++) { acc[ii][0] = 0.f; acc[ii][1] = 0.f; }
            const int tb4 = wrp * 4;                    // this warp's 4 t-rows

            for (int nc = 0; nc < 8; nc++) {
                // stage C[p][nc*64 .. +63] -> Cs (1024 float4, 512 thr x 2)
#pragma unroll
                for (int q = i; q < 1024; q += 512) {
                    int pp = q >> 4, j4 = (q & 15) * 4;
                    float4 cv = *reinterpret_cast<const float4*>(
                        Cm + (size_t)pp * NSTA + nc * 64 + j4);
                    *reinterpret_cast<float4*>(&s->Cs[pp][j4]) = cv;
                }
                __syncthreads();
                const int kb_ = nc * 64;
#pragma unroll
                for (int j = 0; j < 64; j += 4) {
                    float4 xq0 = *reinterpret_cast<const float4*>(&s->X[tb4 + 0][kb_ + j]);
                    float4 xq1 = *reinterpret_cast<const float4*>(&s->X[tb4 + 1][kb_ + j]);
                    float4 xq2 = *reinterpret_cast<const float4*>(&s->X[tb4 + 2][kb_ + j]);
                    float4 xq3 = *reinterpret_cast<const float4*>(&s->X[tb4 + 3][kb_ + j]);
                    float4 c0  = *reinterpret_cast<const float4*>(&s->Cs[lane][j]);
                    float4 c1  = *reinterpret_cast<const float4*>(&s->Cs[lane + 32][j]);
                    acc[0][0] = fmaf(xq0.x, c0.x, acc[0][0]); acc[0][1] = fmaf(xq0.x, c1.x, acc[0][1]);
                    acc[1][0] = fmaf(xq1.x, c0.x, acc[1][0]); acc[1][1] = fmaf(xq1.x, c1.x, acc[1][1]);
                    acc[2][0] = fmaf(xq2.x, c0.x, acc[2][0]); acc[2][1] = fmaf(xq2.x, c1.x, acc[2][1]);
                    acc[3][0] = fmaf(xq3.x, c0.x, acc[3][0]); acc[3][1] = fmaf(xq3.x, c1.x, acc[3][1]);
                    acc[0][0] = fmaf(xq0.y, c0.y, acc[0][0]); acc[0][1] = fmaf(xq0.y, c1.y, acc[0][1]);
                    acc[1][0] = fmaf(xq1.y, c0.y, acc[1][0]); acc[1][1] = fmaf(xq1.y, c1.y, acc[1][1]);
                    acc[2][0] = fmaf(xq2.y, c0.y, acc[2][0]); acc[2][1] = fmaf(xq2.y, c1.y, acc[2][1]);
                    acc[3][0] = fmaf(xq3.y, c0.y, acc[3][0]); acc[3][1] = fmaf(xq3.y, c1.y, acc[3][1]);
                    acc[0][0] = fmaf(xq0.z, c0.z, acc[0][0]); acc[0][1] = fmaf(xq0.z, c1.z, acc[0][1]);
                    acc[1][0] = fmaf(xq1.z, c0.z, acc[1][0]); acc[1][1] = fmaf(xq1.z, c1.z, acc[1][1]);
                    acc[2][0] = fmaf(xq2.z, c0.z, acc[2][0]); acc[2][1] = fmaf(xq2.z, c1.z, acc[2][1]);
                    acc[3][0] = fmaf(xq3.z, c0.z, acc[3][0]); acc[3][1] = fmaf(xq3.z, c1.z, acc[3][1]);
                    acc[0][0] = fmaf(xq0.w, c0.w, acc[0][0]); acc[0][1] = fmaf(xq0.w, c1.w, acc[0][1]);
                    acc[1][0] = fmaf(xq1.w, c0.w, acc[1][0]); acc[1][1] = fmaf(xq1.w, c1.w, acc[1][1]);
                    acc[2][0] = fmaf(xq2.w, c0.w, acc[2][0]); acc[2][1] = fmaf(xq2.w, c1.w, acc[2][1]);
                    acc[3][0] = fmaf(xq3.w, c0.w, acc[3][0]); acc[3][1] = fmaf(xq3.w, c1.w, acc[3][1]);
                }
                __syncthreads();
            }
            // write y tile: rows g*64 + tb4 + ii, cols lane & lane+32
            float* yt = y_b + (size_t)(g * 64 + tb4) * PPO;
#pragma unroll
            for (int ii = 0; ii < 4; ii++) {
                yt[ii * PPO + lane]      = acc[ii][0];
                yt[ii * PPO + lane + 32] = acc[ii][1];
            }
        }

        cp_wait0();
        __syncthreads();
    }
}

// ---------------------------------------------------------------------------
// K4: y += u @ D^T   (small RMW GEMM, K=64)
// ---------------------------------------------------------------------------
__global__ void __launch_bounds__(256) k_du(const float* __restrict__ u,
                                            const float* __restrict__ Dm,
                                            float* __restrict__ y) {
    __shared__ float us[64][65];
    __shared__ float ds[64][65];
    const int r0  = blockIdx.x * 64;
    const int tid = threadIdx.x;

    for (int q = tid; q < 4096; q += 256) ds[q >> 6][q & 63] = Dm[q];
    for (int q = tid; q < 4096; q += 256)
        us[q >> 6][q & 63] = u[(size_t)r0 * MMI + q];
    __syncthreads();

    const int tx = tid & 15;   // p-group
    const int ty = tid >> 4;   // r-group
    float acc[4][4];
#pragma unroll
    for (int ii = 0; ii < 4; ii++)
#pragma unroll
        for (int jj = 0; jj < 4; jj++) acc[ii][jj] = 0.f;

#pragma unroll
    for (int k = 0; k < 64; k++) {
        float av[4], bv[4];
#pragma unroll
        for (int ii = 0; ii < 4; ii++) av[ii] = us[ty * 4 + ii][k];
#pragma unroll
        for (int jj = 0; jj < 4; jj++) bv[jj] = ds[tx * 4 + jj][k];
#pragma unroll
        for (int ii = 0; ii < 4; ii++)
#pragma unroll
            for (int jj = 0; jj < 4; jj++)
                acc[ii][jj] = fmaf(av[ii], bv[jj], acc[ii][jj]);
    }

#pragma unroll
    for (int ii = 0; ii < 4; ii++) {
        float4* yp = reinterpret_cast<float4*>(
            y + (size_t)(r0 + ty * 4 + ii) * PPO + tx * 4);
        float4 vv = *yp;
        vv.x += acc[ii][0]; vv.y += acc[ii][1];
        vv.z += acc[ii][2]; vv.w += acc[ii][3];
        *yp = vv;
    }
}

// ---------------------------------------------------------------------------
extern "C" void kernel_launch(void* const* d_in, const int* in_sizes, int n_in,
                              void* d_out, int out_size) {
    const float* u  = (const float*)d_in[0];
    const float* a  = (const float*)d_in[1];
    const float* Bm = (const float*)d_in[2];
    const float* Cm = (const float*)d_in[3];
    const float* Dm = (const float*)d_in[4];
    float* y = (float*)d_out;
    (void)in_sizes; (void)n_in; (void)out_size;

    k_zero_d<<<(NB * TT / 4) / 256, 256>>>();
    k_bu<<<dim3(NROWS / 128, NSTA / 64), 256>>>(u, Bm);
    k_ziir<<<NB, 512>>>(a);

    cudaFuncSetAttribute(k_fused, cudaFuncAttributeMaxDynamicSharedMemorySize,
                         (int)sizeof(FSmem));
    k_fused<<<NB * NCH, 512, sizeof(FSmem)>>>(a, Cm, y);

    k_du<<<NROWS / 64, 256>>>(u, Dm, y);
}

// round 13
// speedup vs baseline: 1.2289x; 1.2289x over previous
#include <cuda_runtime.h>
#include <cuda_bf16.h>
#include <cstdint>
#include <cstddef>

#define NB    32
#define TT    2048
#define MMI   64
#define PPO   64
#define NSTA  512
#define NROWS (NB * TT)
#define KB    16              // scan trace block (time steps)
#define CHUNK 256             // time chunk per k_x CTA
#define NCH   (TT / CHUNK)    // 8
#define ZK    128             // z-IIR block

#define CS    520             // C bf16 plane row stride (elems): 1040B -> 16B shift/row
#define DS2   72              // D bf16 plane row stride: 144B -> 16B shift/row
#define XS    72              // X stage row stride

__device__ float g_Bu[NROWS * NSTA];
__device__ float g_x [NROWS * NSTA];
__device__ float g_d [NB * TT];
__device__ float g_z [NB * (TT + 1)];
__device__ __align__(16) __nv_bfloat16 g_Chi[64 * CS];
__device__ __align__(16) __nv_bfloat16 g_Clo[64 * CS];
__device__ __align__(16) __nv_bfloat16 g_Dhi[64 * DS2];
__device__ __align__(16) __nv_bfloat16 g_Dlo[64 * DS2];

// ---------------------------------------------------------------------------
__global__ void k_zero_d() {
    int i = blockIdx.x * blockDim.x + threadIdx.x;
    reinterpret_cast<float4*>(g_d)[i] = make_float4(0.f, 0.f, 0.f, 0.f);
}

// ---------------------------------------------------------------------------
// Prep: split C and D into bf16 hi/lo planes with padded strides.
// ---------------------------------------------------------------------------
__global__ void k_split(const float* __restrict__ Cm, const float* __restrict__ Dm) {
    int i = blockIdx.x * 256 + threadIdx.x;
    if (i < 64 * 512) {
        int n = i >> 9, k = i & 511;
        float v = Cm[i];
        __nv_bfloat16 h = __float2bfloat16_rn(v);
        float r = v - __bfloat162float(h);
        g_Chi[n * CS + k] = h;
        g_Clo[n * CS + k] = __float2bfloat16_rn(r);
    }
    if (i < 64 * 64) {
        int n = i >> 6, m = i & 63;
        float v = Dm[i];
        __nv_bfloat16 h = __float2bfloat16_rn(v);
        float r = v - __bfloat162float(h);
        g_Dhi[n * DS2 + m] = h;
        g_Dlo[n * DS2 + m] = __float2bfloat16_rn(r);
    }
}

// ---------------------------------------------------------------------------
// K1: Bu = u @ B^T, fused with anti-diagonal partial sums for d. (unchanged)
// ---------------------------------------------------------------------------
__global__ void __launch_bounds__(256) k_bu(const float* __restrict__ u,
                                            const float* __restrict__ Bm) {
    __shared__ float us[128][33];
    __shared__ float bs[64][33];
    __shared__ float dsh[192];

    const int r0  = blockIdx.x * 128;
    const int n0  = blockIdx.y * 64;
    const int tid = threadIdx.x;
    const int tx  = tid & 15;
    const int ty  = tid >> 4;
    const int lr  = tid >> 3;
    const int lk  = (tid & 7) * 4;

    if (tid < 192) dsh[tid] = 0.f;

    float acc[8][4];
#pragma unroll
    for (int i = 0; i < 8; i++)
#pragma unroll
        for (int j = 0; j < 4; j++) acc[i][j] = 0.0f;

#pragma unroll
    for (int c = 0; c < 2; c++) {
#pragma unroll
        for (int pass = 0; pass < 4; ++pass) {
            int row = lr + pass * 32;
            float4 v = *reinterpret_cast<const float4*>(
                u + (size_t)(r0 + row) * MMI + c * 32 + lk);
            us[row][lk + 0] = v.x; us[row][lk + 1] = v.y;
            us[row][lk + 2] = v.z; us[row][lk + 3] = v.w;
        }
#pragma unroll
        for (int pass = 0; pass < 2; ++pass) {
            int n = lr + pass * 32;
            float4 v = *reinterpret_cast<const float4*>(
                Bm + (size_t)(n0 + n) * MMI + c * 32 + lk);
            bs[n][lk + 0] = v.x; bs[n][lk + 1] = v.y;
            bs[n][lk + 2] = v.z; bs[n][lk + 3] = v.w;
        }
        __syncthreads();
#pragma unroll
        for (int k = 0; k < 32; k++) {
            float av[8], bv[4];
#pragma unroll
            for (int i = 0; i < 8; i++) av[i] = us[ty * 8 + i][k];
#pragma unroll
            for (int j = 0; j < 4; j++) bv[j] = bs[tx * 4 + j][k];
#pragma unroll
            for (int i = 0; i < 8; i++)
#pragma unroll
                for (int j = 0; j < 4; j++)
                    acc[i][j] = fmaf(av[i], bv[j], acc[i][j]);
        }
        __syncthreads();
    }

#pragma unroll
    for (int i = 0; i < 8; i++) {
        float4 v = make_float4(acc[i][0], acc[i][1], acc[i][2], acc[i][3]);
        *reinterpret_cast<float4*>(
            g_Bu + (size_t)(r0 + ty * 8 + i) * NSTA + n0 + tx * 4) = v;
    }

    float dl[11];
#pragma unroll
    for (int q = 0; q < 11; q++) dl[q] = 0.f;
#pragma unroll
    for (int i = 0; i < 8; i++)
#pragma unroll
        for (int j = 0; j < 4; j++) dl[i - j + 3] += acc[i][j];
    const int obase = ty * 8 - tx * 4 + 60;
#pragma unroll
    for (int q = 0; q < 11; q++) atomicAdd(&dsh[obase + q], dl[q]);
    __syncthreads();
    if (tid < 192) {
        int bb  = r0 >> 11;
        int idx = (r0 & 2047) + 448 - n0 + tid;
        if (idx < TT) atomicAdd(&g_d[bb * TT + idx], dsh[tid]);
    }
}

// ---------------------------------------------------------------------------
// K2a: scalar 512-tap IIR per batch (unchanged)
// ---------------------------------------------------------------------------
__global__ void __launch_bounds__(512) k_ziir(const float* __restrict__ a) {
    __shared__ float zb[2561];
    __shared__ float as[512];
    __shared__ float gs[ZK];
    __shared__ float bsol[ZK];

    const int b   = blockIdx.x;
    const int tid = threadIdx.x;

    as[tid] = a[tid];
    for (int i = tid; i < 2561; i += 512) zb[i] = 0.f;
    __syncthreads();

    if (tid < 32) {
        const int l = tid;
        for (int c = 0; c < ZK; c += 32) {
            const int q = c + l;
            float H = 0.f;
            for (int j = q - c + 1; j <= q; j++)
                H += as[j - 1] * gs[q - j];
            float inner = 0.f;
            for (int m = 0; m < 32; m++) {
                float v = -(H + inner);
                if (c == 0 && m == 0) v = 1.f;
                float gval = __shfl_sync(0xffffffffu, v, m);
                if (l == m) gs[q] = gval;
                else if (l > m) inner += as[l - m - 1] * gval;
            }
            __syncwarp();
        }
    }
    __syncthreads();

    const float* dp = g_d + (size_t)b * TT;
    const int k4 = (tid >> 2) + 1;
    const int qq = tid & 3;

    for (int blk = 0; blk < TT / ZK; blk++) {
        const int T0 = blk * ZK;
        const int t  = T0 + k4;
        float H = 0.f;
        for (int j = k4 + qq; j <= 512; j += 4)
            H += as[j - 1] * zb[512 + t - j];
        H += __shfl_xor_sync(0xffffffffu, H, 1);
        H += __shfl_xor_sync(0xffffffffu, H, 2);
        if (qq == 0) bsol[k4 - 1] = dp[t - 1] - H;
        __syncthreads();
        float zv = 0.f;
        for (int m = 1 + qq; m <= k4; m += 4)
            zv += gs[k4 - m] * bsol[m - 1];
        zv += __shfl_xor_sync(0xffffffffu, zv, 1);
        zv += __shfl_xor_sync(0xffffffffu, zv, 2);
        if (qq == 0) zb[512 + t] = zv;
        __syncthreads();
    }

    for (int t = tid; t <= TT; t += 512)
        g_z[(size_t)b * (TT + 1) + t] = zb[512 + t];
}

// ---------------------------------------------------------------------------
// K2b: parallel state materialization (unchanged from R11 best).
// ---------------------------------------------------------------------------
struct XSmem {
    float butile[2][KB * NSTA];
    float xs[2][NSTA];
    float fs[NSTA];
    float zs[2][KB];
};

__device__ __forceinline__ unsigned su32(const void* p) {
    return (unsigned)__cvta_generic_to_shared(p);
}
__device__ __forceinline__ void cp16(void* smem_dst, const void* gsrc) {
    asm volatile("cp.async.cg.shared.global [%0], [%1], 16;"
                 :: "r"(su32(smem_dst)), "l"(gsrc));
}
__device__ __forceinline__ void cp_commit() { asm volatile("cp.async.commit_group;"); }
__device__ __forceinline__ void cp_wait0()  { asm volatile("cp.async.wait_group 0;"); }

__global__ void __launch_bounds__(512, 2) k_x(const float* __restrict__ a) {
    extern __shared__ char raw[];
    XSmem* s = reinterpret_cast<XSmem*>(raw);
    const int b = blockIdx.x >> 3;
    const int c = blockIdx.x & 7;
    const int i = threadIdx.x;

    s->fs[i] = -a[511 - i];
    s->xs[0][i] = 0.f;

    const int warm    = (c * CHUNK < 512) ? c * CHUNK : 512;
    const int base_t  = c * CHUNK - warm;
    const int nblk    = (warm + CHUNK) / KB;
    const int wstore0 = warm / KB;

    const float* bu_g = g_Bu + ((size_t)b * TT + base_t) * NSTA;
    const float* z_g  = g_z + (size_t)b * (TT + 1) + base_t;
    float*       xo   = g_x + (size_t)b * TT * NSTA;

    {
        float* dst = s->butile[0];
#pragma unroll
        for (int r = 0; r < 4; r++) { int q = i + r * 512; cp16(dst + q * 4, bu_g + q * 4); }
        cp_commit(); cp_wait0();
    }
    if (i < KB) s->zs[0][i] = z_g[i];
    __syncthreads();

    for (int w = 0; w < nblk; w++) {
        const int cur = w & 1;
        const float* bu  = s->butile[cur];
        const float* xsc = s->xs[cur];
        const float* zsc = s->zs[cur];

        if (w + 1 < nblk) {
            const float* src = bu_g + (size_t)(w + 1) * KB * NSTA;
            float* dst = s->butile[cur ^ 1];
#pragma unroll
            for (int r = 0; r < 4; r++) { int q = i + r * 512; cp16(dst + q * 4, src + q * 4); }
            cp_commit();
            if (i < KB) s->zs[cur ^ 1][i] = z_g[(size_t)(w + 1) * KB + i];
        }

        const bool st = (w >= wstore0);
        const int  tb = base_t + w * KB;
        float v  = (i >= KB) ? xsc[i - KB]        : 0.f;
        float v2 = (i <  KB) ? xsc[NSTA - KB + i] : 0.f;

#pragma unroll
        for (int k = 1; k <= KB; k++) {
            const float zk = zsc[k - 1];
            int p = i - KB + k;
            if (p == 0) {
                v = s->fs[0] * zk + bu[(k - 1) * NSTA];
                if (st) xo[(size_t)(tb + k - 1) * NSTA] = v;
            } else if (p > 0) {
                v += s->fs[p] * zk + bu[(k - 1) * NSTA + p];
                if (st) xo[(size_t)(tb + k - 1) * NSTA + p] = v;
            }
            if (i < KB) {
                int p2 = NSTA - KB + i + k;
                if (p2 < NSTA) {
                    v2 += s->fs[p2] * zk + bu[(k - 1) * NSTA + p2];
                    if (st) xo[(size_t)(tb + k - 1) * NSTA + p2] = v2;
                }
            }
        }
        s->xs[cur ^ 1][i] = v;
        cp_wait0();
        __syncthreads();
    }
}

// ---------------------------------------------------------------------------
// K3: TENSOR-CORE output GEMM. y = x @ C^T + u @ D^T via bf16 3-split mma.
// CTA = 128 rows x 64 cols, 8 warps (warp = 16 rows). K staged 64-wide:
// 8 stages from x (K=512) + 1 stage from u (K=64, B = D planes).
// ---------------------------------------------------------------------------
struct OSmem {
    __nv_bfloat16 Xhi[128 * XS];   // 18432 B
    __nv_bfloat16 Xlo[128 * XS];   // 18432 B
    __nv_bfloat16 Chi[64 * CS];    // 66560 B
    __nv_bfloat16 Clo[64 * CS];    // 66560 B
    __nv_bfloat16 Dhi[64 * DS2];   // 9216 B
    __nv_bfloat16 Dlo[64 * DS2];   // 9216 B
};                                 // 188416 B

__device__ __forceinline__ unsigned pack_bf16(float a, float b) {
    __nv_bfloat162 t = __floats2bfloat162_rn(a, b);
    return *reinterpret_cast<unsigned*>(&t);
}

__device__ __forceinline__ void mma_bf16(float& d0, float& d1, float& d2, float& d3,
                                         unsigned a0, unsigned a1, unsigned a2, unsigned a3,
                                         unsigned b0, unsigned b1) {
    asm volatile(
        "mma.sync.aligned.m16n8k16.row.col.f32.bf16.bf16.f32 "
        "{%0,%1,%2,%3},{%4,%5,%6,%7},{%8,%9},{%0,%1,%2,%3};\n"
        : "+f"(d0), "+f"(d1), "+f"(d2), "+f"(d3)
        : "r"(a0), "r"(a1), "r"(a2), "r"(a3), "r"(b0), "r"(b1));
}

__global__ void __launch_bounds__(256, 1) k_out_tc(const float* __restrict__ u,
                                                   float* __restrict__ y) {
    extern __shared__ char raw[];
    OSmem* s = reinterpret_cast<OSmem*>(raw);
    const int tid  = threadIdx.x;
    const int lane = tid & 31;
    const int wrp  = tid >> 5;          // 0..7
    const int g    = lane >> 2;         // 0..7
    const int tig  = lane & 3;          // 0..3
    const size_t row0 = (size_t)blockIdx.x * 128;

    // ---- stage C/D bf16 planes into smem via cp.async ----
    for (int q = tid; q < 4160; q += 256) {
        cp16((char*)s->Chi + q * 16, (const char*)g_Chi + q * 16);
        cp16((char*)s->Clo + q * 16, (const char*)g_Clo + q * 16);
    }
    for (int q = tid; q < 576; q += 256) {
        cp16((char*)s->Dhi + q * 16, (const char*)g_Dhi + q * 16);
        cp16((char*)s->Dlo + q * 16, (const char*)g_Dlo + q * 16);
    }
    cp_commit();

    // ---- prefetch stage 0 of X ----
    const int pr = tid >> 1;            // row 0..127
    const int ph = (tid & 1) * 8;       // float4 half offset
    const float* xrow = g_x + (row0 + pr) * NSTA;
    const float* urow = u   + (row0 + pr) * MMI;
    float4 pf[8];
#pragma unroll
    for (int j = 0; j < 8; j++)
        pf[j] = *reinterpret_cast<const float4*>(xrow + (ph + j) * 4);

    cp_wait0();
    __syncthreads();

    float acc[8][4];
#pragma unroll
    for (int nt = 0; nt < 8; nt++)
#pragma unroll
        for (int q = 0; q < 4; q++) acc[nt][q] = 0.f;

    const int r0w = wrp * 16;

    for (int st = 0; st < 9; st++) {
        // ---- convert prefetched fp32 tile -> bf16 hi/lo planes in smem ----
#pragma unroll
        for (int j = 0; j < 8; j++) {
            float4 v = pf[j];
            __nv_bfloat16 hx = __float2bfloat16_rn(v.x);
            __nv_bfloat16 hy = __float2bfloat16_rn(v.y);
            __nv_bfloat16 hz = __float2bfloat16_rn(v.z);
            __nv_bfloat16 hw = __float2bfloat16_rn(v.w);
            float lx = v.x - __bfloat162float(hx);
            float ly = v.y - __bfloat162float(hy);
            float lz = v.z - __bfloat162float(hz);
            float lw = v.w - __bfloat162float(hw);
            unsigned h01 = (__bfloat16_as_ushort(hx)) | ((unsigned)__bfloat16_as_ushort(hy) << 16);
            unsigned h23 = (__bfloat16_as_ushort(hz)) | ((unsigned)__bfloat16_as_ushort(hw) << 16);
            unsigned l01 = pack_bf16(lx, ly);
            unsigned l23 = pack_bf16(lz, lw);
            int cb = (ph + j) * 4;
            *reinterpret_cast<unsigned*>(&s->Xhi[pr * XS + cb])     = h01;
            *reinterpret_cast<unsigned*>(&s->Xhi[pr * XS + cb + 2]) = h23;
            *reinterpret_cast<unsigned*>(&s->Xlo[pr * XS + cb])     = l01;
            *reinterpret_cast<unsigned*>(&s->Xlo[pr * XS + cb + 2]) = l23;
        }
        __syncthreads();

        // ---- prefetch next stage while mma runs ----
        if (st < 8) {
            const float* src = (st < 7) ? (xrow + (st + 1) * 64) : urow;
#pragma unroll
            for (int j = 0; j < 8; j++)
                pf[j] = *reinterpret_cast<const float4*>(src + (ph + j) * 4);
        }

        // ---- mma phase ----
        const __nv_bfloat16* Bh;
        const __nv_bfloat16* Bl;
        int bstr, kofs;
        if (st < 8) { Bh = s->Chi; Bl = s->Clo; bstr = CS;  kofs = st * 64; }
        else        { Bh = s->Dhi; Bl = s->Dlo; bstr = DS2; kofs = 0; }

#pragma unroll
        for (int kc = 0; kc < 4; kc++) {
            const int c0 = kc * 16 + 2 * tig;
            unsigned ah0 = *reinterpret_cast<const unsigned*>(&s->Xhi[(r0w + g)     * XS + c0]);
            unsigned ah1 = *reinterpret_cast<const unsigned*>(&s->Xhi[(r0w + g + 8) * XS + c0]);
            unsigned ah2 = *reinterpret_cast<const unsigned*>(&s->Xhi[(r0w + g)     * XS + c0 + 8]);
            unsigned ah3 = *reinterpret_cast<const unsigned*>(&s->Xhi[(r0w + g + 8) * XS + c0 + 8]);
            unsigned al0 = *reinterpret_cast<const unsigned*>(&s->Xlo[(r0w + g)     * XS + c0]);
            unsigned al1 = *reinterpret_cast<const unsigned*>(&s->Xlo[(r0w + g + 8) * XS + c0]);
            unsigned al2 = *reinterpret_cast<const unsigned*>(&s->Xlo[(r0w + g)     * XS + c0 + 8]);
            unsigned al3 = *reinterpret_cast<const unsigned*>(&s->Xlo[(r0w + g + 8) * XS + c0 + 8]);
#pragma unroll
            for (int nt = 0; nt < 8; nt++) {
                const int bn = nt * 8 + g;
                unsigned bh0 = *reinterpret_cast<const unsigned*>(&Bh[bn * bstr + kofs + c0]);
                unsigned bh1 = *reinterpret_cast<const unsigned*>(&Bh[bn * bstr + kofs + c0 + 8]);
                unsigned bl0 = *reinterpret_cast<const unsigned*>(&Bl[bn * bstr + kofs + c0]);
                unsigned bl1 = *reinterpret_cast<const unsigned*>(&Bl[bn * bstr + kofs + c0 + 8]);
                mma_bf16(acc[nt][0], acc[nt][1], acc[nt][2], acc[nt][3],
                         ah0, ah1, ah2, ah3, bh0, bh1);     // hi*hi
                mma_bf16(acc[nt][0], acc[nt][1], acc[nt][2], acc[nt][3],
                         ah0, ah1, ah2, ah3, bl0, bl1);     // hi*lo
                mma_bf16(acc[nt][0], acc[nt][1], acc[nt][2], acc[nt][3],
                         al0, al1, al2, al3, bh0, bh1);     // lo*hi
            }
        }
        __syncthreads();
    }

    // ---- epilogue ----
    float* yb = y + (row0 + r0w) * PPO;
#pragma unroll
    for (int nt = 0; nt < 8; nt++) {
        const int col = nt * 8 + 2 * tig;
        *reinterpret_cast<float2*>(&yb[g * PPO + col])       = make_float2(acc[nt][0], acc[nt][1]);
        *reinterpret_cast<float2*>(&yb[(g + 8) * PPO + col]) = make_float2(acc[nt][2], acc[nt][3]);
    }
}

// ---------------------------------------------------------------------------
extern "C" void kernel_launch(void* const* d_in, const int* in_sizes, int n_in,
                              void* d_out, int out_size) {
    const float* u  = (const float*)d_in[0];
    const float* a  = (const float*)d_in[1];
    const float* Bm = (const float*)d_in[2];
    const float* Cm = (const float*)d_in[3];
    const float* Dm = (const float*)d_in[4];
    float* y = (float*)d_out;
    (void)in_sizes; (void)n_in; (void)out_size;

    k_zero_d<<<(NB * TT / 4) / 256, 256>>>();
    k_split<<<128, 256>>>(Cm, Dm);
    k_bu<<<dim3(NROWS / 128, NSTA / 64), 256>>>(u, Bm);
    k_ziir<<<NB, 512>>>(a);

    cudaFuncSetAttribute(k_x, cudaFuncAttributeMaxDynamicSharedMemorySize,
                         (int)sizeof(XSmem));
    k_x<<<NB * NCH, 512, sizeof(XSmem)>>>(a);

    cudaFuncSetAttribute(k_out_tc, cudaFuncAttributeMaxDynamicSharedMemorySize,
                         (int)sizeof(OSmem));
    k_out_tc<<<NROWS / 128, 256, sizeof(OSmem)>>>(u, y);
}

// round 14
// speedup vs baseline: 1.2495x; 1.0167x over previous
#include <cuda_runtime.h>
#include <cuda_bf16.h>
#include <cstdint>
#include <cstddef>

#define NB    32
#define TT    2048
#define MMI   64
#define PPO   64
#define NSTA  512
#define NROWS (NB * TT)
#define KB    16              // scan trace block (time steps)
#define CHUNK 256             // time chunk per k_x CTA
#define NCH   (TT / CHUNK)    // 8
#define ZK    128             // z-IIR block
#define XS    72              // X stage row stride (bf16 elems)
#define CSS   72              // C chunk row stride (bf16 elems)

__device__ float g_Bu[NROWS * NSTA];
__device__ float g_x [NROWS * NSTA];
__device__ float g_d [NB * TT];
__device__ float g_z [NB * (TT + 1)];
__device__ __align__(16) __nv_bfloat16 g_Chi[64 * 512];
__device__ __align__(16) __nv_bfloat16 g_Clo[64 * 512];
__device__ __align__(16) __nv_bfloat16 g_Dhi[64 * 64];
__device__ __align__(16) __nv_bfloat16 g_Dlo[64 * 64];

// ---------------------------------------------------------------------------
__global__ void k_zero_d() {
    int i = blockIdx.x * blockDim.x + threadIdx.x;
    reinterpret_cast<float4*>(g_d)[i] = make_float4(0.f, 0.f, 0.f, 0.f);
}

// ---------------------------------------------------------------------------
// Prep: split C and D into bf16 hi/lo planes (unpadded, chunk-loadable).
// ---------------------------------------------------------------------------
__global__ void k_split(const float* __restrict__ Cm, const float* __restrict__ Dm) {
    int i = blockIdx.x * 256 + threadIdx.x;
    if (i < 64 * 512) {
        float v = Cm[i];
        __nv_bfloat16 h = __float2bfloat16_rn(v);
        g_Chi[i] = h;
        g_Clo[i] = __float2bfloat16_rn(v - __bfloat162float(h));
    }
    if (i < 64 * 64) {
        float v = Dm[i];
        __nv_bfloat16 h = __float2bfloat16_rn(v);
        g_Dhi[i] = h;
        g_Dlo[i] = __float2bfloat16_rn(v - __bfloat162float(h));
    }
}

// ---------------------------------------------------------------------------
// K1: Bu = u @ B^T, fused with anti-diagonal partial sums for d. (unchanged)
// ---------------------------------------------------------------------------
__global__ void __launch_bounds__(256) k_bu(const float* __restrict__ u,
                                            const float* __restrict__ Bm) {
    __shared__ float us[128][33];
    __shared__ float bs[64][33];
    __shared__ float dsh[192];

    const int r0  = blockIdx.x * 128;
    const int n0  = blockIdx.y * 64;
    const int tid = threadIdx.x;
    const int tx  = tid & 15;
    const int ty  = tid >> 4;
    const int lr  = tid >> 3;
    const int lk  = (tid & 7) * 4;

    if (tid < 192) dsh[tid] = 0.f;

    float acc[8][4];
#pragma unroll
    for (int i = 0; i < 8; i++)
#pragma unroll
        for (int j = 0; j < 4; j++) acc[i][j] = 0.0f;

#pragma unroll
    for (int c = 0; c < 2; c++) {
#pragma unroll
        for (int pass = 0; pass < 4; ++pass) {
            int row = lr + pass * 32;
            float4 v = *reinterpret_cast<const float4*>(
                u + (size_t)(r0 + row) * MMI + c * 32 + lk);
            us[row][lk + 0] = v.x; us[row][lk + 1] = v.y;
            us[row][lk + 2] = v.z; us[row][lk + 3] = v.w;
        }
#pragma unroll
        for (int pass = 0; pass < 2; ++pass) {
            int n = lr + pass * 32;
            float4 v = *reinterpret_cast<const float4*>(
                Bm + (size_t)(n0 + n) * MMI + c * 32 + lk);
            bs[n][lk + 0] = v.x; bs[n][lk + 1] = v.y;
            bs[n][lk + 2] = v.z; bs[n][lk + 3] = v.w;
        }
        __syncthreads();
#pragma unroll
        for (int k = 0; k < 32; k++) {
            float av[8], bv[4];
#pragma unroll
            for (int i = 0; i < 8; i++) av[i] = us[ty * 8 + i][k];
#pragma unroll
            for (int j = 0; j < 4; j++) bv[j] = bs[tx * 4 + j][k];
#pragma unroll
            for (int i = 0; i < 8; i++)
#pragma unroll
                for (int j = 0; j < 4; j++)
                    acc[i][j] = fmaf(av[i], bv[j], acc[i][j]);
        }
        __syncthreads();
    }

#pragma unroll
    for (int i = 0; i < 8; i++) {
        float4 v = make_float4(acc[i][0], acc[i][1], acc[i][2], acc[i][3]);
        *reinterpret_cast<float4*>(
            g_Bu + (size_t)(r0 + ty * 8 + i) * NSTA + n0 + tx * 4) = v;
    }

    float dl[11];
#pragma unroll
    for (int q = 0; q < 11; q++) dl[q] = 0.f;
#pragma unroll
    for (int i = 0; i < 8; i++)
#pragma unroll
        for (int j = 0; j < 4; j++) dl[i - j + 3] += acc[i][j];
    const int obase = ty * 8 - tx * 4 + 60;
#pragma unroll
    for (int q = 0; q < 11; q++) atomicAdd(&dsh[obase + q], dl[q]);
    __syncthreads();
    if (tid < 192) {
        int bb  = r0 >> 11;
        int idx = (r0 & 2047) + 448 - n0 + tid;
        if (idx < TT) atomicAdd(&g_d[bb * TT + idx], dsh[tid]);
    }
}

// ---------------------------------------------------------------------------
// K2a: scalar 512-tap IIR per batch. UNROLLED: fixed-trip predicated loops
// with 4 rotating accumulators (chain depth 128 -> 32).
// ---------------------------------------------------------------------------
__global__ void __launch_bounds__(512) k_ziir(const float* __restrict__ a) {
    __shared__ float zb[2561];    // zb[512+s] = z_s (zero-init: s<=0 pad AND future)
    __shared__ float as[512];
    __shared__ float gs[ZK];
    __shared__ float bsol[ZK];

    const int b   = blockIdx.x;
    const int tid = threadIdx.x;

    as[tid] = a[tid];
    for (int i = tid; i < 2561; i += 512) zb[i] = 0.f;
    __syncthreads();

    if (tid < 32) {
        const int l = tid;
        for (int c = 0; c < ZK; c += 32) {
            const int q = c + l;
            float H = 0.f;
            for (int j = q - c + 1; j <= q; j++)
                H += as[j - 1] * gs[q - j];
            float inner = 0.f;
            for (int m = 0; m < 32; m++) {
                float v = -(H + inner);
                if (c == 0 && m == 0) v = 1.f;
                float gval = __shfl_sync(0xffffffffu, v, m);
                if (l == m) gs[q] = gval;
                else if (l > m) inner += as[l - m - 1] * gval;
            }
            __syncwarp();
        }
    }
    __syncthreads();

    const float* dp = g_d + (size_t)b * TT;
    const int k4 = (tid >> 2) + 1;  // position in block 1..128
    const int qq = tid & 3;

    for (int blk = 0; blk < TT / ZK; blk++) {
        const int T0 = blk * ZK;
        const int t  = T0 + k4;

        // history: taps j in [k4, 512]; fixed-trip over residue class qq+1 mod 4
        float h0 = 0.f, h1 = 0.f, h2 = 0.f, h3 = 0.f;
#pragma unroll
        for (int jj = 0; jj < 128; jj++) {
            const int j = qq + 1 + 4 * jj;
            // j < k4 reads a future zb slot, which is still 0 -> contributes 0,
            // but predicate anyway to keep exact semantics.
            float v = (j >= k4) ? as[j - 1] * zb[512 + t - j] : 0.f;
            if ((jj & 3) == 0) h0 += v;
            else if ((jj & 3) == 1) h1 += v;
            else if ((jj & 3) == 2) h2 += v;
            else h3 += v;
        }
        float H = (h0 + h1) + (h2 + h3);
        H += __shfl_xor_sync(0xffffffffu, H, 1);
        H += __shfl_xor_sync(0xffffffffu, H, 2);
        if (qq == 0) bsol[k4 - 1] = dp[t - 1] - H;
        __syncthreads();

        // z_block = G * b: taps m in [1, k4]
        float z0 = 0.f, z1 = 0.f, z2 = 0.f, z3 = 0.f;
#pragma unroll
        for (int mm = 0; mm < 32; mm++) {
            const int m = qq + 1 + 4 * mm;
            float v = (m <= k4) ? gs[k4 - m] * bsol[m - 1] : 0.f;
            if ((mm & 3) == 0) z0 += v;
            else if ((mm & 3) == 1) z1 += v;
            else if ((mm & 3) == 2) z2 += v;
            else z3 += v;
        }
        float zv = (z0 + z1) + (z2 + z3);
        zv += __shfl_xor_sync(0xffffffffu, zv, 1);
        zv += __shfl_xor_sync(0xffffffffu, zv, 2);
        if (qq == 0) zb[512 + t] = zv;
        __syncthreads();
    }

    for (int t = tid; t <= TT; t += 512)
        g_z[(size_t)b * (TT + 1) + t] = zb[512 + t];
}

// ---------------------------------------------------------------------------
// K2b: parallel state materialization (unchanged).
// ---------------------------------------------------------------------------
struct XSmem {
    float butile[2][KB * NSTA];
    float xs[2][NSTA];
    float fs[NSTA];
    float zs[2][KB];
};

__device__ __forceinline__ unsigned su32(const void* p) {
    return (unsigned)__cvta_generic_to_shared(p);
}
__device__ __forceinline__ void cp16(void* smem_dst, const void* gsrc) {
    asm volatile("cp.async.cg.shared.global [%0], [%1], 16;"
                 :: "r"(su32(smem_dst)), "l"(gsrc));
}
__device__ __forceinline__ void cp_commit() { asm volatile("cp.async.commit_group;"); }
__device__ __forceinline__ void cp_wait0()  { asm volatile("cp.async.wait_group 0;"); }
__device__ __forceinline__ void cp_wait1()  { asm volatile("cp.async.wait_group 1;"); }

__global__ void __launch_bounds__(512, 2) k_x(const float* __restrict__ a) {
    extern __shared__ char raw[];
    XSmem* s = reinterpret_cast<XSmem*>(raw);
    const int b = blockIdx.x >> 3;
    const int c = blockIdx.x & 7;
    const int i = threadIdx.x;

    s->fs[i] = -a[511 - i];
    s->xs[0][i] = 0.f;

    const int warm    = (c * CHUNK < 512) ? c * CHUNK : 512;
    const int base_t  = c * CHUNK - warm;
    const int nblk    = (warm + CHUNK) / KB;
    const int wstore0 = warm / KB;

    const float* bu_g = g_Bu + ((size_t)b * TT + base_t) * NSTA;
    const float* z_g  = g_z + (size_t)b * (TT + 1) + base_t;
    float*       xo   = g_x + (size_t)b * TT * NSTA;

    {
        float* dst = s->butile[0];
#pragma unroll
        for (int r = 0; r < 4; r++) { int q = i + r * 512; cp16(dst + q * 4, bu_g + q * 4); }
        cp_commit(); cp_wait0();
    }
    if (i < KB) s->zs[0][i] = z_g[i];
    __syncthreads();

    for (int w = 0; w < nblk; w++) {
        const int cur = w & 1;
        const float* bu  = s->butile[cur];
        const float* xsc = s->xs[cur];
        const float* zsc = s->zs[cur];

        if (w + 1 < nblk) {
            const float* src = bu_g + (size_t)(w + 1) * KB * NSTA;
            float* dst = s->butile[cur ^ 1];
#pragma unroll
            for (int r = 0; r < 4; r++) { int q = i + r * 512; cp16(dst + q * 4, src + q * 4); }
            cp_commit();
            if (i < KB) s->zs[cur ^ 1][i] = z_g[(size_t)(w + 1) * KB + i];
        }

        const bool st = (w >= wstore0);
        const int  tb = base_t + w * KB;
        float v  = (i >= KB) ? xsc[i - KB]        : 0.f;
        float v2 = (i <  KB) ? xsc[NSTA - KB + i] : 0.f;

#pragma unroll
        for (int k = 1; k <= KB; k++) {
            const float zk = zsc[k - 1];
            int p = i - KB + k;
            if (p == 0) {
                v = s->fs[0] * zk + bu[(k - 1) * NSTA];
                if (st) xo[(size_t)(tb + k - 1) * NSTA] = v;
            } else if (p > 0) {
                v += s->fs[p] * zk + bu[(k - 1) * NSTA + p];
                if (st) xo[(size_t)(tb + k - 1) * NSTA + p] = v;
            }
            if (i < KB) {
                int p2 = NSTA - KB + i + k;
                if (p2 < NSTA) {
                    v2 += s->fs[p2] * zk + bu[(k - 1) * NSTA + p2];
                    if (st) xo[(size_t)(tb + k - 1) * NSTA + p2] = v2;
                }
            }
        }
        s->xs[cur ^ 1][i] = v;
        cp_wait0();
        __syncthreads();
    }
}

// ---------------------------------------------------------------------------
// K3: TENSOR-CORE output GEMM, C streamed per 64-col chunk (double-buffered).
// smem 72 KB -> 2 CTAs/SM. CTA = 128 rows x 64 cols, 8 warps.
// 8 K-stages from x (K=512) + 1 stage from u (B = D planes).
// ---------------------------------------------------------------------------
struct OSmem {
    __nv_bfloat16 Xhi[128 * XS];      // 18432 B
    __nv_bfloat16 Xlo[128 * XS];      // 18432 B
    __nv_bfloat16 Ch[2][64 * CSS];    // 18432 B
    __nv_bfloat16 Cl[2][64 * CSS];    // 18432 B
};                                    // 73728 B

__device__ __forceinline__ unsigned pack_bf16(float a, float b) {
    __nv_bfloat162 t = __floats2bfloat162_rn(a, b);
    return *reinterpret_cast<unsigned*>(&t);
}

__device__ __forceinline__ void mma_bf16(float& d0, float& d1, float& d2, float& d3,
                                         unsigned a0, unsigned a1, unsigned a2, unsigned a3,
                                         unsigned b0, unsigned b1) {
    asm volatile(
        "mma.sync.aligned.m16n8k16.row.col.f32.bf16.bf16.f32 "
        "{%0,%1,%2,%3},{%4,%5,%6,%7},{%8,%9},{%0,%1,%2,%3};\n"
        : "+f"(d0), "+f"(d1), "+f"(d2), "+f"(d3)
        : "r"(a0), "r"(a1), "r"(a2), "r"(a3), "r"(b0), "r"(b1));
}

__global__ void __launch_bounds__(256, 2) k_out_tc(const float* __restrict__ u,
                                                   float* __restrict__ y) {
    extern __shared__ char raw[];
    OSmem* s = reinterpret_cast<OSmem*>(raw);
    const int tid  = threadIdx.x;
    const int lane = tid & 31;
    const int wrp  = tid >> 5;          // 0..7
    const int g    = lane >> 2;         // 0..7
    const int tig  = lane & 3;          // 0..3
    const size_t row0 = (size_t)blockIdx.x * 128;

    // ---- C/D chunk issue helper: stage st -> buffer st&1 ----
    auto issueC = [&](int st) {
        const __nv_bfloat16* srcH;
        const __nv_bfloat16* srcL;
        int rstr, cof;
        if (st < 8) { srcH = g_Chi; srcL = g_Clo; rstr = 512; cof = st * 64; }
        else        { srcH = g_Dhi; srcL = g_Dlo; rstr = 64;  cof = 0; }
        const int buf = st & 1;
        for (int q = tid; q < 512; q += 256) {
            int n = q >> 3, h = (q & 7) * 8;
            cp16(&s->Ch[buf][n * CSS + h], srcH + (size_t)n * rstr + cof + h);
            cp16(&s->Cl[buf][n * CSS + h], srcL + (size_t)n * rstr + cof + h);
        }
        cp_commit();
    };

    issueC(0);

    // ---- prefetch stage 0 of X ----
    const int pr = tid >> 1;            // row 0..127
    const int ph = (tid & 1) * 8;       // float4 half offset
    const float* xrow = g_x + (row0 + pr) * NSTA;
    const float* urow = u   + (row0 + pr) * MMI;
    float4 pf[8];
#pragma unroll
    for (int j = 0; j < 8; j++)
        pf[j] = *reinterpret_cast<const float4*>(xrow + (ph + j) * 4);

    float acc[8][4];
#pragma unroll
    for (int nt = 0; nt < 8; nt++)
#pragma unroll
        for (int q = 0; q < 4; q++) acc[nt][q] = 0.f;

    const int r0w = wrp * 16;

    for (int st = 0; st < 9; st++) {
        // ---- convert prefetched fp32 X tile -> bf16 hi/lo planes in smem ----
#pragma unroll
        for (int j = 0; j < 8; j++) {
            float4 v = pf[j];
            __nv_bfloat16 hx = __float2bfloat16_rn(v.x);
            __nv_bfloat16 hy = __float2bfloat16_rn(v.y);
            __nv_bfloat16 hz = __float2bfloat16_rn(v.z);
            __nv_bfloat16 hw = __float2bfloat16_rn(v.w);
            float lx = v.x - __bfloat162float(hx);
            float ly = v.y - __bfloat162float(hy);
            float lz = v.z - __bfloat162float(hz);
            float lw = v.w - __bfloat162float(hw);
            unsigned h01 = (__bfloat16_as_ushort(hx)) | ((unsigned)__bfloat16_as_ushort(hy) << 16);
            unsigned h23 = (__bfloat16_as_ushort(hz)) | ((unsigned)__bfloat16_as_ushort(hw) << 16);
            unsigned l01 = pack_bf16(lx, ly);
            unsigned l23 = pack_bf16(lz, lw);
            int cb = (ph + j) * 4;
            *reinterpret_cast<unsigned*>(&s->Xhi[pr * XS + cb])     = h01;
            *reinterpret_cast<unsigned*>(&s->Xhi[pr * XS + cb + 2]) = h23;
            *reinterpret_cast<unsigned*>(&s->Xlo[pr * XS + cb])     = l01;
            *reinterpret_cast<unsigned*>(&s->Xlo[pr * XS + cb + 2]) = l23;
        }

        if (st < 8) { issueC(st + 1); cp_wait1(); }
        else        { cp_wait0(); }
        __syncthreads();   // X planes + current C chunk visible

        // ---- prefetch next X stage while mma runs ----
        if (st < 8) {
            const float* src = (st < 7) ? (xrow + (st + 1) * 64) : urow;
#pragma unroll
            for (int j = 0; j < 8; j++)
                pf[j] = *reinterpret_cast<const float4*>(src + (ph + j) * 4);
        }

        // ---- mma phase ----
        const __nv_bfloat16* Bh = s->Ch[st & 1];
        const __nv_bfloat16* Bl = s->Cl[st & 1];

#pragma unroll
        for (int kc = 0; kc < 4; kc++) {
            const int c0 = kc * 16 + 2 * tig;
            unsigned ah0 = *reinterpret_cast<const unsigned*>(&s->Xhi[(r0w + g)     * XS + c0]);
            unsigned ah1 = *reinterpret_cast<const unsigned*>(&s->Xhi[(r0w + g + 8) * XS + c0]);
            unsigned ah2 = *reinterpret_cast<const unsigned*>(&s->Xhi[(r0w + g)     * XS + c0 + 8]);
            unsigned ah3 = *reinterpret_cast<const unsigned*>(&s->Xhi[(r0w + g + 8) * XS + c0 + 8]);
            unsigned al0 = *reinterpret_cast<const unsigned*>(&s->Xlo[(r0w + g)     * XS + c0]);
            unsigned al1 = *reinterpret_cast<const unsigned*>(&s->Xlo[(r0w + g + 8) * XS + c0]);
            unsigned al2 = *reinterpret_cast<const unsigned*>(&s->Xlo[(r0w + g)     * XS + c0 + 8]);
            unsigned al3 = *reinterpret_cast<const unsigned*>(&s->Xlo[(r0w + g + 8) * XS + c0 + 8]);
#pragma unroll
            for (int nt = 0; nt < 8; nt++) {
                const int bn = nt * 8 + g;
                unsigned bh0 = *reinterpret_cast<const unsigned*>(&Bh[bn * CSS + c0]);
                unsigned bh1 = *reinterpret_cast<const unsigned*>(&Bh[bn * CSS + c0 + 8]);
                unsigned bl0 = *reinterpret_cast<const unsigned*>(&Bl[bn * CSS + c0]);
                unsigned bl1 = *reinterpret_cast<const unsigned*>(&Bl[bn * CSS + c0 + 8]);
                mma_bf16(acc[nt][0], acc[nt][1], acc[nt][2], acc[nt][3],
                         ah0, ah1, ah2, ah3, bh0, bh1);     // hi*hi
                mma_bf16(acc[nt][0], acc[nt][1], acc[nt][2], acc[nt][3],
                         ah0, ah1, ah2, ah3, bl0, bl1);     // hi*lo
                mma_bf16(acc[nt][0], acc[nt][1], acc[nt][2], acc[nt][3],
                         al0, al1, al2, al3, bh0, bh1);     // lo*hi
            }
        }
        __syncthreads();   // done reading X before next convert overwrites
    }

    // ---- epilogue ----
    float* yb = y + (row0 + r0w) * PPO;
#pragma unroll
    for (int nt = 0; nt < 8; nt++) {
        const int col = nt * 8 + 2 * tig;
        *reinterpret_cast<float2*>(&yb[g * PPO + col])       = make_float2(acc[nt][0], acc[nt][1]);
        *reinterpret_cast<float2*>(&yb[(g + 8) * PPO + col]) = make_float2(acc[nt][2], acc[nt][3]);
    }
}

// ---------------------------------------------------------------------------
extern "C" void kernel_launch(void* const* d_in, const int* in_sizes, int n_in,
                              void* d_out, int out_size) {
    const float* u  = (const float*)d_in[0];
    const float* a  = (const float*)d_in[1];
    const float* Bm = (const float*)d_in[2];
    const float* Cm = (const float*)d_in[3];
    const float* Dm = (const float*)d_in[4];
    float* y = (float*)d_out;
    (void)in_sizes; (void)n_in; (void)out_size;

    k_zero_d<<<(NB * TT / 4) / 256, 256>>>();
    k_split<<<128, 256>>>(Cm, Dm);
    k_bu<<<dim3(NROWS / 128, NSTA / 64), 256>>>(u, Bm);
    k_ziir<<<NB, 512>>>(a);

    cudaFuncSetAttribute(k_x, cudaFuncAttributeMaxDynamicSharedMemorySize,
                         (int)sizeof(XSmem));
    k_x<<<NB * NCH, 512, sizeof(XSmem)>>>(a);

    cudaFuncSetAttribute(k_out_tc, cudaFuncAttributeMaxDynamicSharedMemorySize,
                         (int)sizeof(OSmem));
    k_out_tc<<<NROWS / 128, 256, sizeof(OSmem)>>>(u, y);
}

// round 17
// speedup vs baseline: 1.3187x; 1.0554x over previous
#include <cuda_runtime.h>
#include <cuda_bf16.h>
#include <cstdint>
#include <cstddef>

#define NB    32
#define TT    2048
#define MMI   64
#define PPO   64
#define NSTA  512
#define NROWS (NB * TT)
#define KB    16              // scan trace block (time steps)
#define CHUNK 256             // time chunk per k_x CTA
#define NCH   (TT / CHUNK)    // 8
#define ZK    128             // z-IIR block
#define XS    72              // X stage row stride (bf16 elems)
#define CSS   72              // C chunk row stride (bf16 elems)
#define HPS   132             // hp row stride (floats, %4==0)

__device__ float g_Bu[NROWS * NSTA];
__device__ float g_x [NROWS * NSTA];
__device__ float g_d [NB * TT];
__device__ float g_z [NB * (TT + 1)];
__device__ __align__(16) __nv_bfloat16 g_Chi[64 * 512];
__device__ __align__(16) __nv_bfloat16 g_Clo[64 * 512];
__device__ __align__(16) __nv_bfloat16 g_Dhi[64 * 64];
__device__ __align__(16) __nv_bfloat16 g_Dlo[64 * 64];

// ---------------------------------------------------------------------------
__global__ void k_zero_d() {
    int i = blockIdx.x * blockDim.x + threadIdx.x;
    reinterpret_cast<float4*>(g_d)[i] = make_float4(0.f, 0.f, 0.f, 0.f);
}

// ---------------------------------------------------------------------------
__global__ void k_split(const float* __restrict__ Cm, const float* __restrict__ Dm) {
    int i = blockIdx.x * 256 + threadIdx.x;
    if (i < 64 * 512) {
        float v = Cm[i];
        __nv_bfloat16 h = __float2bfloat16_rn(v);
        g_Chi[i] = h;
        g_Clo[i] = __float2bfloat16_rn(v - __bfloat162float(h));
    }
    if (i < 64 * 64) {
        float v = Dm[i];
        __nv_bfloat16 h = __float2bfloat16_rn(v);
        g_Dhi[i] = h;
        g_Dlo[i] = __float2bfloat16_rn(v - __bfloat162float(h));
    }
}

// ---------------------------------------------------------------------------
// K1: Bu = u @ B^T, fused with anti-diagonal partial sums for d. (unchanged)
// ---------------------------------------------------------------------------
__global__ void __launch_bounds__(256) k_bu(const float* __restrict__ u,
                                            const float* __restrict__ Bm) {
    __shared__ float us[128][33];
    __shared__ float bs[64][33];
    __shared__ float dsh[192];

    const int r0  = blockIdx.x * 128;
    const int n0  = blockIdx.y * 64;
    const int tid = threadIdx.x;
    const int tx  = tid & 15;
    const int ty  = tid >> 4;
    const int lr  = tid >> 3;
    const int lk  = (tid & 7) * 4;

    if (tid < 192) dsh[tid] = 0.f;

    float acc[8][4];
#pragma unroll
    for (int i = 0; i < 8; i++)
#pragma unroll
        for (int j = 0; j < 4; j++) acc[i][j] = 0.0f;

#pragma unroll
    for (int c = 0; c < 2; c++) {
#pragma unroll
        for (int pass = 0; pass < 4; ++pass) {
            int row = lr + pass * 32;
            float4 v = *reinterpret_cast<const float4*>(
                u + (size_t)(r0 + row) * MMI + c * 32 + lk);
            us[row][lk + 0] = v.x; us[row][lk + 1] = v.y;
            us[row][lk + 2] = v.z; us[row][lk + 3] = v.w;
        }
#pragma unroll
        for (int pass = 0; pass < 2; ++pass) {
            int n = lr + pass * 32;
            float4 v = *reinterpret_cast<const float4*>(
                Bm + (size_t)(n0 + n) * MMI + c * 32 + lk);
            bs[n][lk + 0] = v.x; bs[n][lk + 1] = v.y;
            bs[n][lk + 2] = v.z; bs[n][lk + 3] = v.w;
        }
        __syncthreads();
#pragma unroll
        for (int k = 0; k < 32; k++) {
            float av[8], bv[4];
#pragma unroll
            for (int i = 0; i < 8; i++) av[i] = us[ty * 8 + i][k];
#pragma unroll
            for (int j = 0; j < 4; j++) bv[j] = bs[tx * 4 + j][k];
#pragma unroll
            for (int i = 0; i < 8; i++)
#pragma unroll
                for (int j = 0; j < 4; j++)
                    acc[i][j] = fmaf(av[i], bv[j], acc[i][j]);
        }
        __syncthreads();
    }

#pragma unroll
    for (int i = 0; i < 8; i++) {
        float4 v = make_float4(acc[i][0], acc[i][1], acc[i][2], acc[i][3]);
        *reinterpret_cast<float4*>(
            g_Bu + (size_t)(r0 + ty * 8 + i) * NSTA + n0 + tx * 4) = v;
    }

    float dl[11];
#pragma unroll
    for (int q = 0; q < 11; q++) dl[q] = 0.f;
#pragma unroll
    for (int i = 0; i < 8; i++)
#pragma unroll
        for (int j = 0; j < 4; j++) dl[i - j + 3] += acc[i][j];
    const int obase = ty * 8 - tx * 4 + 60;
#pragma unroll
    for (int q = 0; q < 11; q++) atomicAdd(&dsh[obase + q], dl[q]);
    __syncthreads();
    if (tid < 192) {
        int bb  = r0 >> 11;
        int idx = (r0 & 2047) + 448 - n0 + tid;
        if (idx < TT) atomicAdd(&g_d[bb * TT + idx], dsh[tid]);
    }
}

// ---------------------------------------------------------------------------
// K2a: scalar 512-tap IIR per batch — reuse-restructured, 16B-aligned smem.
// ---------------------------------------------------------------------------
__global__ void __launch_bounds__(512) k_ziir(const float* __restrict__ a) {
    __shared__ __align__(16) float zb[2561];   // zb[512+s] = z_s; zero pad
    __shared__ __align__(16) float as[512];
    __shared__ __align__(16) float gsp[256];   // [0..127]=0, [128..255]=g
    __shared__ __align__(16) float bsol[ZK];
    __shared__ __align__(16) float hp[16][HPS];

    const int b   = blockIdx.x;
    const int tid = threadIdx.x;

    as[tid] = a[tid];
    for (int i = tid; i < 2561; i += 512) zb[i] = 0.f;
    if (tid < 256) gsp[tid] = 0.f;
    __syncthreads();

    // impulse response g[0..127] into gsp[128..255] (warp 0, warp-serial)
    if (tid < 32) {
        float* gs = gsp + 128;
        const int l = tid;
        for (int c = 0; c < ZK; c += 32) {
            const int q = c + l;
            float H = 0.f;
            for (int j = q - c + 1; j <= q; j++)
                H += as[j - 1] * gs[q - j];
            float inner = 0.f;
            for (int m = 0; m < 32; m++) {
                float v = -(H + inner);
                if (c == 0 && m == 0) v = 1.f;
                float gval = __shfl_sync(0xffffffffu, v, m);
                if (l == m) gs[q] = gval;
                else if (l > m) inner += as[l - m - 1] * gval;
            }
            __syncwarp();
        }
    }
    __syncthreads();

    const float* dp = g_d + (size_t)b * TT;
    const int q  = tid & 31;       // output group: k = k0..k0+3
    const int w  = tid >> 5;       // tap slice
    const int k0 = 4 * q + 1;

    for (int blk = 0; blk < TT / ZK; blk++) {
        const int T0 = blk * ZK;

        // ======== H phase: H_k = sum_{j=k}^{512} a[j-1] * z[T0+k-j] ========
        {
            const int jhi  = w * 32 + 32;
            const int base = 512 + T0 + k0;
            const int al   = base - jhi - 1;      // multiple of 4
            float rw[8];
            *reinterpret_cast<float4*>(&rw[0]) =
                *reinterpret_cast<const float4*>(&zb[al]);
            *reinterpret_cast<float4*>(&rw[4]) =
                *reinterpret_cast<const float4*>(&zb[al + 4]);
            float h0 = 0.f, h1 = 0.f, h2 = 0.f, h3 = 0.f;
#pragma unroll
            for (int it = 0; it < 32; it++) {
                if (it && (it & 3) == 0) {
                    rw[0] = rw[4]; rw[1] = rw[5]; rw[2] = rw[6]; rw[3] = rw[7];
                    *reinterpret_cast<float4*>(&rw[4]) =
                        *reinterpret_cast<const float4*>(&zb[al + 4 + it]);
                }
                const int j  = jhi - it;
                const float av = as[j - 1];       // warp-uniform broadcast
                const int o  = 1 + (it & 3);
                if (j >= k0)     h0 = fmaf(av, rw[o],     h0);
                if (j >= k0 + 1) h1 = fmaf(av, rw[o + 1], h1);
                if (j >= k0 + 2) h2 = fmaf(av, rw[o + 2], h2);
                if (j >= k0 + 3) h3 = fmaf(av, rw[o + 3], h3);
            }
            *reinterpret_cast<float4*>(&hp[w][4 * q]) = make_float4(h0, h1, h2, h3);
        }
        __syncthreads();

        if (tid < ZK) {
            float H = 0.f;
#pragma unroll
            for (int ww = 0; ww < 16; ww++) H += hp[ww][tid];
            bsol[tid] = dp[T0 + tid] - H;
        }
        __syncthreads();

        // ======== G phase: z_k = sum_{m=1}^{k} g[k-m] * b_{m-1} ========
        {
            const int mhi   = 8 * w + 8;
            const int base2 = 128 + k0;
            const int al2   = base2 - mhi - 1;    // multiple of 4
            float rw[8];
            *reinterpret_cast<float4*>(&rw[0]) =
                *reinterpret_cast<const float4*>(&gsp[al2]);
            *reinterpret_cast<float4*>(&rw[4]) =
                *reinterpret_cast<const float4*>(&gsp[al2 + 4]);
            float z0 = 0.f, z1 = 0.f, z2 = 0.f, z3 = 0.f;
#pragma unroll
            for (int it = 0; it < 8; it++) {
                if (it == 4) {
                    rw[0] = rw[4]; rw[1] = rw[5]; rw[2] = rw[6]; rw[3] = rw[7];
                    *reinterpret_cast<float4*>(&rw[4]) =
                        *reinterpret_cast<const float4*>(&gsp[al2 + 8]);
                }
                const int m  = mhi - it;
                const float bv = bsol[m - 1];     // warp-uniform broadcast
                const int o  = 1 + (it & 3);
                z0 = fmaf(rw[o],     bv, z0);
                z1 = fmaf(rw[o + 1], bv, z1);
                z2 = fmaf(rw[o + 2], bv, z2);
                z3 = fmaf(rw[o + 3], bv, z3);
            }
            *reinterpret_cast<float4*>(&hp[w][4 * q]) = make_float4(z0, z1, z2, z3);
        }
        __syncthreads();

        if (tid < ZK) {
            float zv = 0.f;
#pragma unroll
            for (int ww = 0; ww < 16; ww++) zv += hp[ww][tid];
            zb[512 + T0 + tid + 1] = zv;
        }
        __syncthreads();
    }

    for (int t = tid; t <= TT; t += 512)
        g_z[(size_t)b * (TT + 1) + t] = zb[512 + t];
}

// ---------------------------------------------------------------------------
// K2b: parallel state materialization (unchanged).
// ---------------------------------------------------------------------------
struct XSmem {
    float butile[2][KB * NSTA];
    float xs[2][NSTA];
    float fs[NSTA];
    float zs[2][KB];
};

__device__ __forceinline__ unsigned su32(const void* p) {
    return (unsigned)__cvta_generic_to_shared(p);
}
__device__ __forceinline__ void cp16(void* smem_dst, const void* gsrc) {
    asm volatile("cp.async.cg.shared.global [%0], [%1], 16;"
                 :: "r"(su32(smem_dst)), "l"(gsrc));
}
__device__ __forceinline__ void cp_commit() { asm volatile("cp.async.commit_group;"); }
__device__ __forceinline__ void cp_wait0()  { asm volatile("cp.async.wait_group 0;"); }
__device__ __forceinline__ void cp_wait1()  { asm volatile("cp.async.wait_group 1;"); }

__global__ void __launch_bounds__(512, 2) k_x(const float* __restrict__ a) {
    extern __shared__ char raw[];
    XSmem* s = reinterpret_cast<XSmem*>(raw);
    const int b = blockIdx.x >> 3;
    const int c = blockIdx.x & 7;
    const int i = threadIdx.x;

    s->fs[i] = -a[511 - i];
    s->xs[0][i] = 0.f;

    const int warm    = (c * CHUNK < 512) ? c * CHUNK : 512;
    const int base_t  = c * CHUNK - warm;
    const int nblk    = (warm + CHUNK) / KB;
    const int wstore0 = warm / KB;

    const float* bu_g = g_Bu + ((size_t)b * TT + base_t) * NSTA;
    const float* z_g  = g_z + (size_t)b * (TT + 1) + base_t;
    float*       xo   = g_x + (size_t)b * TT * NSTA;

    {
        float* dst = s->butile[0];
#pragma unroll
        for (int r = 0; r < 4; r++) { int q = i + r * 512; cp16(dst + q * 4, bu_g + q * 4); }
        cp_commit(); cp_wait0();
    }
    if (i < KB) s->zs[0][i] = z_g[i];
    __syncthreads();

    for (int w = 0; w < nblk; w++) {
        const int cur = w & 1;
        const float* bu  = s->butile[cur];
        const float* xsc = s->xs[cur];
        const float* zsc = s->zs[cur];

        if (w + 1 < nblk) {
            const float* src = bu_g + (size_t)(w + 1) * KB * NSTA;
            float* dst = s->butile[cur ^ 1];
#pragma unroll
            for (int r = 0; r < 4; r++) { int q = i + r * 512; cp16(dst + q * 4, src + q * 4); }
            cp_commit();
            if (i < KB) s->zs[cur ^ 1][i] = z_g[(size_t)(w + 1) * KB + i];
        }

        const bool st = (w >= wstore0);
        const int  tb = base_t + w * KB;
        float v  = (i >= KB) ? xsc[i - KB]        : 0.f;
        float v2 = (i <  KB) ? xsc[NSTA - KB + i] : 0.f;

#pragma unroll
        for (int k = 1; k <= KB; k++) {
            const float zk = zsc[k - 1];
            int p = i - KB + k;
            if (p == 0) {
                v = s->fs[0] * zk + bu[(k - 1) * NSTA];
                if (st) xo[(size_t)(tb + k - 1) * NSTA] = v;
            } else if (p > 0) {
                v += s->fs[p] * zk + bu[(k - 1) * NSTA + p];
                if (st) xo[(size_t)(tb + k - 1) * NSTA + p] = v;
            }
            if (i < KB) {
                int p2 = NSTA - KB + i + k;
                if (p2 < NSTA) {
                    v2 += s->fs[p2] * zk + bu[(k - 1) * NSTA + p2];
                    if (st) xo[(size_t)(tb + k - 1) * NSTA + p2] = v2;
                }
            }
        }
        s->xs[cur ^ 1][i] = v;
        cp_wait0();
        __syncthreads();
    }
}

// ---------------------------------------------------------------------------
// K3: TENSOR-CORE output GEMM, C streamed per 64-col chunk (unchanged).
// ---------------------------------------------------------------------------
struct OSmem {
    __nv_bfloat16 Xhi[128 * XS];
    __nv_bfloat16 Xlo[128 * XS];
    __nv_bfloat16 Ch[2][64 * CSS];
    __nv_bfloat16 Cl[2][64 * CSS];
};

__device__ __forceinline__ unsigned pack_bf16(float a, float b) {
    __nv_bfloat162 t = __floats2bfloat162_rn(a, b);
    return *reinterpret_cast<unsigned*>(&t);
}

__device__ __forceinline__ void mma_bf16(float& d0, float& d1, float& d2, float& d3,
                                         unsigned a0, unsigned a1, unsigned a2, unsigned a3,
                                         unsigned b0, unsigned b1) {
    asm volatile(
        "mma.sync.aligned.m16n8k16.row.col.f32.bf16.bf16.f32 "
        "{%0,%1,%2,%3},{%4,%5,%6,%7},{%8,%9},{%0,%1,%2,%3};\n"
        : "+f"(d0), "+f"(d1), "+f"(d2), "+f"(d3)
        : "r"(a0), "r"(a1), "r"(a2), "r"(a3), "r"(b0), "r"(b1));
}

__global__ void __launch_bounds__(256, 2) k_out_tc(const float* __restrict__ u,
                                                   float* __restrict__ y) {
    extern __shared__ char raw[];
    OSmem* s = reinterpret_cast<OSmem*>(raw);
    const int tid  = threadIdx.x;
    const int lane = tid & 31;
    const int wrp  = tid >> 5;
    const int g    = lane >> 2;
    const int tig  = lane & 3;
    const size_t row0 = (size_t)blockIdx.x * 128;

    auto issueC = [&](int st) {
        const __nv_bfloat16* srcH;
        const __nv_bfloat16* srcL;
        int rstr, cof;
        if (st < 8) { srcH = g_Chi; srcL = g_Clo; rstr = 512; cof = st * 64; }
        else        { srcH = g_Dhi; srcL = g_Dlo; rstr = 64;  cof = 0; }
        const int buf = st & 1;
        for (int q = tid; q < 512; q += 256) {
            int n = q >> 3, h = (q & 7) * 8;
            cp16(&s->Ch[buf][n * CSS + h], srcH + (size_t)n * rstr + cof + h);
            cp16(&s->Cl[buf][n * CSS + h], srcL + (size_t)n * rstr + cof + h);
        }
        cp_commit();
    };

    issueC(0);

    const int pr = tid >> 1;
    const int ph = (tid & 1) * 8;
    const float* xrow = g_x + (row0 + pr) * NSTA;
    const float* urow = u   + (row0 + pr) * MMI;
    float4 pf[8];
#pragma unroll
    for (int j = 0; j < 8; j++)
        pf[j] = *reinterpret_cast<const float4*>(xrow + (ph + j) * 4);

    float acc[8][4];
#pragma unroll
    for (int nt = 0; nt < 8; nt++)
#pragma unroll
        for (int q = 0; q < 4; q++) acc[nt][q] = 0.f;

    const int r0w = wrp * 16;

    for (int st = 0; st < 9; st++) {
#pragma unroll
        for (int j = 0; j < 8; j++) {
            float4 v = pf[j];
            __nv_bfloat16 hx = __float2bfloat16_rn(v.x);
            __nv_bfloat16 hy = __float2bfloat16_rn(v.y);
            __nv_bfloat16 hz = __float2bfloat16_rn(v.z);
            __nv_bfloat16 hw = __float2bfloat16_rn(v.w);
            float lx = v.x - __bfloat162float(hx);
            float ly = v.y - __bfloat162float(hy);
            float lz = v.z - __bfloat162float(hz);
            float lw = v.w - __bfloat162float(hw);
            unsigned h01 = (__bfloat16_as_ushort(hx)) | ((unsigned)__bfloat16_as_ushort(hy) << 16);
            unsigned h23 = (__bfloat16_as_ushort(hz)) | ((unsigned)__bfloat16_as_ushort(hw) << 16);
            unsigned l01 = pack_bf16(lx, ly);
            unsigned l23 = pack_bf16(lz, lw);
            int cb = (ph + j) * 4;
            *reinterpret_cast<unsigned*>(&s->Xhi[pr * XS + cb])     = h01;
            *reinterpret_cast<unsigned*>(&s->Xhi[pr * XS + cb + 2]) = h23;
            *reinterpret_cast<unsigned*>(&s->Xlo[pr * XS + cb])     = l01;
            *reinterpret_cast<unsigned*>(&s->Xlo[pr * XS + cb + 2]) = l23;
        }

        if (st < 8) { issueC(st + 1); cp_wait1(); }
        else        { cp_wait0(); }
        __syncthreads();

        if (st < 8) {
            const float* src = (st < 7) ? (xrow + (st + 1) * 64) : urow;
#pragma unroll
            for (int j = 0; j < 8; j++)
                pf[j] = *reinterpret_cast<const float4*>(src + (ph + j) * 4);
        }

        const __nv_bfloat16* Bh = s->Ch[st & 1];
        const __nv_bfloat16* Bl = s->Cl[st & 1];

#pragma unroll
        for (int kc = 0; kc < 4; kc++) {
            const int c0 = kc * 16 + 2 * tig;
            unsigned ah0 = *reinterpret_cast<const unsigned*>(&s->Xhi[(r0w + g)     * XS + c0]);
            unsigned ah1 = *reinterpret_cast<const unsigned*>(&s->Xhi[(r0w + g + 8) * XS + c0]);
            unsigned ah2 = *reinterpret_cast<const unsigned*>(&s->Xhi[(r0w + g)     * XS + c0 + 8]);
            unsigned ah3 = *reinterpret_cast<const unsigned*>(&s->Xhi[(r0w + g + 8) * XS + c0 + 8]);
            unsigned al0 = *reinterpret_cast<const unsigned*>(&s->Xlo[(r0w + g)     * XS + c0]);
            unsigned al1 = *reinterpret_cast<const unsigned*>(&s->Xlo[(r0w + g + 8) * XS + c0]);
            unsigned al2 = *reinterpret_cast<const unsigned*>(&s->Xlo[(r0w + g)     * XS + c0 + 8]);
            unsigned al3 = *reinterpret_cast<const unsigned*>(&s->Xlo[(r0w + g + 8) * XS + c0 + 8]);
#pragma unroll
            for (int nt = 0; nt < 8; nt++) {
                const int bn = nt * 8 + g;
                unsigned bh0 = *reinterpret_cast<const unsigned*>(&Bh[bn * CSS + c0]);
                unsigned bh1 = *reinterpret_cast<const unsigned*>(&Bh[bn * CSS + c0 + 8]);
                unsigned bl0 = *reinterpret_cast<const unsigned*>(&Bl[bn * CSS + c0]);
                unsigned bl1 = *reinterpret_cast<const unsigned*>(&Bl[bn * CSS + c0 + 8]);
                mma_bf16(acc[nt][0], acc[nt][1], acc[nt][2], acc[nt][3],
                         ah0, ah1, ah2, ah3, bh0, bh1);
                mma_bf16(acc[nt][0], acc[nt][1], acc[nt][2], acc[nt][3],
                         ah0, ah1, ah2, ah3, bl0, bl1);
                mma_bf16(acc[nt][0], acc[nt][1], acc[nt][2], acc[nt][3],
                         al0, al1, al2, al3, bh0, bh1);
            }
        }
        __syncthreads();
    }

    float* yb = y + (row0 + r0w) * PPO;
#pragma unroll
    for (int nt = 0; nt < 8; nt++) {
        const int col = nt * 8 + 2 * tig;
        *reinterpret_cast<float2*>(&yb[g * PPO + col])       = make_float2(acc[nt][0], acc[nt][1]);
        *reinterpret_cast<float2*>(&yb[(g + 8) * PPO + col]) = make_float2(acc[nt][2], acc[nt][3]);
    }
}

// ---------------------------------------------------------------------------
extern "C" void kernel_launch(void* const* d_in, const int* in_sizes, int n_in,
                              void* d_out, int out_size) {
    const float* u  = (const float*)d_in[0];
    const float* a  = (const float*)d_in[1];
    const float* Bm = (const float*)d_in[2];
    const float* Cm = (const float*)d_in[3];
    const float* Dm = (const float*)d_in[4];
    float* y = (float*)d_out;
    (void)in_sizes; (void)n_in; (void)out_size;

    k_zero_d<<<(NB * TT / 4) / 256, 256>>>();
    k_split<<<128, 256>>>(Cm, Dm);
    k_bu<<<dim3(NROWS / 128, NSTA / 64), 256>>>(u, Bm);
    k_ziir<<<NB, 512>>>(a);

    cudaFuncSetAttribute(k_x, cudaFuncAttributeMaxDynamicSharedMemorySize,
                         (int)sizeof(XSmem));
    k_x<<<NB * NCH, 512, sizeof(XSmem)>>>(a);

    cudaFuncSetAttribute(k_out_tc, cudaFuncAttributeMaxDynamicSharedMemorySize,
                         (int)sizeof(OSmem));
    k_out_tc<<<NROWS / 128, 256, sizeof(OSmem)>>>(u, y);
}